// round 1
// baseline (speedup 1.0000x reference)
#include <cuda_runtime.h>
#include <math_constants.h>

#define N_ROWS 8192
#define DIM    1024
#define NCLS   1000

// ---------------- scratch (device globals: allocation-free) ----------------
__device__ float g_q [N_ROWS * DIM];
__device__ float g_k [N_ROWS * DIM];
__device__ float g_v [N_ROWS * DIM];
__device__ float g_xr[N_ROWS * DIM];
__device__ float g_S [(size_t)N_ROWS * N_ROWS];   // 256 MB scores
__device__ float g_a [N_ROWS * DIM];
__device__ float g_m [N_ROWS * DIM];

// ---------------- tiled SGEMM: C = A[MxK] @ B[KxN] (+bias) ----------------
#define BM 128
#define BN 128
#define BK 8
#define TM 8
#define TN 8

__global__ void __launch_bounds__(256)
gemm_nn(const float* __restrict__ A, const float* __restrict__ B,
        const float* __restrict__ bias, float* __restrict__ C,
        int M, int N, int K)
{
    __shared__ float As[BK][BM];
    __shared__ float Bs[BK][BN];

    const int tid = threadIdx.x;
    const int tx = tid % 16;           // 16 * TN = 128 cols
    const int ty = tid / 16;           // 16 * TM = 128 rows
    const int nbase = blockIdx.x * BN;
    const int mbase = blockIdx.y * BM;

    const int rowA = tid >> 1;              // 0..127
    const int colA = (tid & 1) * 4;         // 0 or 4
    const int rowB = tid >> 5;              // 0..7
    const int colB = (tid & 31) * 4;        // 0..124

    const float* Ab = A + (size_t)mbase * K;

    float acc[TM][TN];
    #pragma unroll
    for (int i = 0; i < TM; i++)
        #pragma unroll
        for (int j = 0; j < TN; j++) acc[i][j] = 0.f;

    for (int k0 = 0; k0 < K; k0 += BK) {
        // A tile -> transposed smem
        float4 av = *(const float4*)(Ab + (size_t)rowA * K + k0 + colA);
        As[colA + 0][rowA] = av.x;
        As[colA + 1][rowA] = av.y;
        As[colA + 2][rowA] = av.z;
        As[colA + 3][rowA] = av.w;
        // B tile (guard N for the 1000-col epilogue GEMM)
        int bn = nbase + colB;
        const float* Bp = B + (size_t)(k0 + rowB) * N + bn;
        float4 bv;
        if (bn + 3 < N) {
            bv = *(const float4*)Bp;
        } else {
            bv.x = (bn + 0 < N) ? Bp[0] : 0.f;
            bv.y = (bn + 1 < N) ? Bp[1] : 0.f;
            bv.z = (bn + 2 < N) ? Bp[2] : 0.f;
            bv.w = (bn + 3 < N) ? Bp[3] : 0.f;
        }
        *(float4*)&Bs[rowB][colB] = bv;
        __syncthreads();

        #pragma unroll
        for (int kk = 0; kk < BK; kk++) {
            float ar[TM], br[TN];
            float4 a0 = *(const float4*)&As[kk][ty * TM];
            float4 a1 = *(const float4*)&As[kk][ty * TM + 4];
            ar[0]=a0.x; ar[1]=a0.y; ar[2]=a0.z; ar[3]=a0.w;
            ar[4]=a1.x; ar[5]=a1.y; ar[6]=a1.z; ar[7]=a1.w;
            float4 b0 = *(const float4*)&Bs[kk][tx * TN];
            float4 b1 = *(const float4*)&Bs[kk][tx * TN + 4];
            br[0]=b0.x; br[1]=b0.y; br[2]=b0.z; br[3]=b0.w;
            br[4]=b1.x; br[5]=b1.y; br[6]=b1.z; br[7]=b1.w;
            #pragma unroll
            for (int i = 0; i < TM; i++)
                #pragma unroll
                for (int j = 0; j < TN; j++)
                    acc[i][j] += ar[i] * br[j];
        }
        __syncthreads();
    }

    #pragma unroll
    for (int i = 0; i < TM; i++) {
        int r = mbase + ty * TM + i;
        #pragma unroll
        for (int j = 0; j < TN; j++) {
            int c = nbase + tx * TN + j;
            if (c < N) {
                float val = acc[i][j];
                if (bias) val += bias[c];
                C[(size_t)r * N + c] = val;
            }
        }
    }
}

// ---------------- NT GEMM: C = scale * (A[MxK] @ B[NxK]^T) ----------------
__global__ void __launch_bounds__(256)
gemm_nt_scale(const float* __restrict__ A, const float* __restrict__ B,
              float* __restrict__ C, int M, int N, int K, float scale)
{
    __shared__ float As[BK][BM];
    __shared__ float Bs[BK][BN];

    const int tid = threadIdx.x;
    const int tx = tid % 16;
    const int ty = tid / 16;
    const int nbase = blockIdx.x * BN;
    const int mbase = blockIdx.y * BM;

    const int rowT = tid >> 1;              // 0..127
    const int colT = (tid & 1) * 4;         // 0 or 4 (K offset)

    const float* Ab = A + (size_t)mbase * K;
    const float* Bb = B + (size_t)nbase * K;

    float acc[TM][TN];
    #pragma unroll
    for (int i = 0; i < TM; i++)
        #pragma unroll
        for (int j = 0; j < TN; j++) acc[i][j] = 0.f;

    for (int k0 = 0; k0 < K; k0 += BK) {
        float4 av = *(const float4*)(Ab + (size_t)rowT * K + k0 + colT);
        As[colT + 0][rowT] = av.x;
        As[colT + 1][rowT] = av.y;
        As[colT + 2][rowT] = av.z;
        As[colT + 3][rowT] = av.w;
        float4 bv = *(const float4*)(Bb + (size_t)rowT * K + k0 + colT);
        Bs[colT + 0][rowT] = bv.x;
        Bs[colT + 1][rowT] = bv.y;
        Bs[colT + 2][rowT] = bv.z;
        Bs[colT + 3][rowT] = bv.w;
        __syncthreads();

        #pragma unroll
        for (int kk = 0; kk < BK; kk++) {
            float ar[TM], br[TN];
            float4 a0 = *(const float4*)&As[kk][ty * TM];
            float4 a1 = *(const float4*)&As[kk][ty * TM + 4];
            ar[0]=a0.x; ar[1]=a0.y; ar[2]=a0.z; ar[3]=a0.w;
            ar[4]=a1.x; ar[5]=a1.y; ar[6]=a1.z; ar[7]=a1.w;
            float4 b0 = *(const float4*)&Bs[kk][tx * TN];
            float4 b1 = *(const float4*)&Bs[kk][tx * TN + 4];
            br[0]=b0.x; br[1]=b0.y; br[2]=b0.z; br[3]=b0.w;
            br[4]=b1.x; br[5]=b1.y; br[6]=b1.z; br[7]=b1.w;
            #pragma unroll
            for (int i = 0; i < TM; i++)
                #pragma unroll
                for (int j = 0; j < TN; j++)
                    acc[i][j] += ar[i] * br[j];
        }
        __syncthreads();
    }

    #pragma unroll
    for (int i = 0; i < TM; i++) {
        int r = mbase + ty * TM + i;
        #pragma unroll
        for (int j = 0; j < TN; j++) {
            int c = nbase + tx * TN + j;
            C[(size_t)r * N + c] = acc[i][j] * scale;
        }
    }
}

// ---------------- single-pass row softmax over 8192 cols ----------------
__global__ void __launch_bounds__(256)
softmax_rows(float* __restrict__ S)
{
    const int row = blockIdx.x;
    float* p = S + (size_t)row * N_ROWS;
    const int tid = threadIdx.x;

    float v[32];
    float mx = -CUDART_INF_F;
    #pragma unroll
    for (int i = 0; i < 32; i++) {
        v[i] = p[tid + i * 256];
        mx = fmaxf(mx, v[i]);
    }
    // reduce max
    __shared__ float red[8];
    #pragma unroll
    for (int o = 16; o > 0; o >>= 1) mx = fmaxf(mx, __shfl_xor_sync(0xffffffffu, mx, o));
    if ((tid & 31) == 0) red[tid >> 5] = mx;
    __syncthreads();
    if (tid < 8) {
        float m = red[tid];
        #pragma unroll
        for (int o = 4; o > 0; o >>= 1) m = fmaxf(m, __shfl_xor_sync(0xffu, m, o));
        if (tid == 0) red[0] = m;
    }
    __syncthreads();
    mx = red[0];
    __syncthreads();

    float sum = 0.f;
    #pragma unroll
    for (int i = 0; i < 32; i++) {
        v[i] = __expf(v[i] - mx);
        sum += v[i];
    }
    // reduce sum
    #pragma unroll
    for (int o = 16; o > 0; o >>= 1) sum += __shfl_xor_sync(0xffffffffu, sum, o);
    if ((tid & 31) == 0) red[tid >> 5] = sum;
    __syncthreads();
    if (tid < 8) {
        float s = red[tid];
        #pragma unroll
        for (int o = 4; o > 0; o >>= 1) s += __shfl_xor_sync(0xffu, s, o);
        if (tid == 0) red[0] = s;
    }
    __syncthreads();
    const float inv = 1.f / red[0];

    #pragma unroll
    for (int i = 0; i < 32; i++) p[tid + i * 256] = v[i] * inv;
}

// ---------------- beta gate + mix, one block per row ----------------
__global__ void __launch_bounds__(256)
beta_mix(const float* __restrict__ a, const float* __restrict__ xr,
         const float* __restrict__ Wb, const float* __restrict__ bb,
         float* __restrict__ Mout)
{
    const int row = blockIdx.x;
    const int tid = threadIdx.x;
    const float* ap = a  + (size_t)row * DIM;
    const float* xp = xr + (size_t)row * DIM;

    float partial = 0.f;
    #pragma unroll
    for (int i = tid; i < DIM; i += 256) {
        float av = ap[i], xv = xp[i];
        partial += av * Wb[i] + xv * Wb[DIM + i] + (av - xv) * Wb[2 * DIM + i];
    }
    __shared__ float red[8];
    #pragma unroll
    for (int o = 16; o > 0; o >>= 1) partial += __shfl_xor_sync(0xffffffffu, partial, o);
    if ((tid & 31) == 0) red[tid >> 5] = partial;
    __syncthreads();
    __shared__ float s_beta;
    if (tid == 0) {
        float t = 0.f;
        #pragma unroll
        for (int w = 0; w < 8; w++) t += red[w];
        t += bb[0];
        s_beta = 1.f / (1.f + expf(-t));
    }
    __syncthreads();
    const float beta = s_beta;

    float* mp = Mout + (size_t)row * DIM;
    #pragma unroll
    for (int i = tid; i < DIM; i += 256)
        mp[i] = beta * xp[i] + (1.f - beta) * ap[i];
}

// ---------------- launch ----------------
extern "C" void kernel_launch(void* const* d_in, const int* in_sizes, int n_in,
                              void* d_out, int out_size)
{
    const float* x      = (const float*)d_in[0];
    const float* W_skip = (const float*)d_in[1];
    const float* b_skip = (const float*)d_in[2];
    const float* W_q    = (const float*)d_in[3];
    const float* b_q    = (const float*)d_in[4];
    const float* W_k    = (const float*)d_in[5];
    const float* b_k    = (const float*)d_in[6];
    const float* W_v    = (const float*)d_in[7];
    const float* b_v    = (const float*)d_in[8];
    const float* W_beta = (const float*)d_in[9];
    const float* b_beta = (const float*)d_in[10];
    const float* W_fc   = (const float*)d_in[11];
    const float* b_fc   = (const float*)d_in[12];
    float* out = (float*)d_out;

    float *q, *k, *v, *xr, *S, *a, *m;
    cudaGetSymbolAddress((void**)&q,  g_q);
    cudaGetSymbolAddress((void**)&k,  g_k);
    cudaGetSymbolAddress((void**)&v,  g_v);
    cudaGetSymbolAddress((void**)&xr, g_xr);
    cudaGetSymbolAddress((void**)&S,  g_S);
    cudaGetSymbolAddress((void**)&a,  g_a);
    cudaGetSymbolAddress((void**)&m,  g_m);

    dim3 blk(256);
    dim3 gProj(DIM / BN, N_ROWS / BM);                 // 8 x 64
    gemm_nn<<<gProj, blk>>>(x, W_q,    b_q,    q,  N_ROWS, DIM, DIM);
    gemm_nn<<<gProj, blk>>>(x, W_k,    b_k,    k,  N_ROWS, DIM, DIM);
    gemm_nn<<<gProj, blk>>>(x, W_v,    b_v,    v,  N_ROWS, DIM, DIM);
    gemm_nn<<<gProj, blk>>>(x, W_skip, b_skip, xr, N_ROWS, DIM, DIM);

    dim3 gScore(N_ROWS / BN, N_ROWS / BM);             // 64 x 64
    gemm_nt_scale<<<gScore, blk>>>(q, k, S, N_ROWS, N_ROWS, DIM, 1.0f / 32.0f);

    softmax_rows<<<N_ROWS, blk>>>(S);

    gemm_nn<<<gProj, blk>>>(S, v, nullptr, a, N_ROWS, DIM, N_ROWS);

    beta_mix<<<N_ROWS, blk>>>(a, xr, W_beta, b_beta, m);

    dim3 gFc((NCLS + BN - 1) / BN, N_ROWS / BM);       // 8 x 64
    gemm_nn<<<gFc, blk>>>(m, W_fc, b_fc, out, N_ROWS, NCLS, DIM);
}

// round 4
// speedup vs baseline: 4.2413x; 4.2413x over previous
#include <cuda_runtime.h>
#include <math_constants.h>
#include <cstdint>

#define N_ROWS 8192
#define DIM    1024
#define NCLS   1000

// ---- mma.sync tf32 GEMM tile config ----
#define BM 128
#define BN 128
#define BK 32
#define STAGES 3
#define A_TILE_FLOATS (BM * BK)                       // 4096
#define B_TILE_FLOATS (BN * BK)                       // 4096
#define STAGE_FLOATS  (A_TILE_FLOATS + B_TILE_FLOATS) // 8192
#define DYN_SMEM      (STAGES * STAGE_FLOATS * 4)     // 96 KB

// ---------------- scratch (device globals: allocation-free) ----------------
__device__ float g_xt [N_ROWS * DIM];
__device__ float g_q  [N_ROWS * DIM];
__device__ float g_k  [N_ROWS * DIM];
__device__ float g_v  [N_ROWS * DIM];
__device__ float g_xr [N_ROWS * DIM];
__device__ float g_a  [N_ROWS * DIM];
__device__ float g_m  [N_ROWS * DIM];
__device__ float g_vT [DIM * N_ROWS];
__device__ float g_S  [(size_t)N_ROWS * N_ROWS];   // 256 MB scores
__device__ float g_WqT [DIM * DIM];
__device__ float g_WkT [DIM * DIM];
__device__ float g_WvT [DIM * DIM];
__device__ float g_WsT [DIM * DIM];
__device__ float g_WfcT[NCLS * DIM];

// ================= helpers =================
__device__ __forceinline__ float tf32r(float x) {
    uint32_t u;
    asm("cvt.rna.tf32.f32 %0, %1;" : "=r"(u) : "f"(x));
    return __uint_as_float(u);
}
__device__ __forceinline__ uint32_t smem_u32(const void* p) {
    uint32_t a;
    asm("{ .reg .u64 t; cvta.to.shared.u64 t, %1; cvt.u32.u64 %0, t; }" : "=r"(a) : "l"(p));
    return a;
}
// conflict-free tf32-fragment swizzle: element (row r, k) -> float offset
__device__ __forceinline__ int swz(int r, int k) {
    return r * BK + (k ^ ((r & 7) << 2));
}
__device__ __forceinline__ void cp16(uint32_t saddr, const float* g) {
    asm volatile("cp.async.cg.shared.global [%0], [%1], 16;" :: "r"(saddr), "l"(g));
}
__device__ __forceinline__ void cp16z(uint32_t saddr, const float* g, int valid) {
    int sz = valid ? 16 : 0;
    asm volatile("cp.async.cg.shared.global [%0], [%1], 16, %2;" :: "r"(saddr), "l"(g), "r"(sz));
}
__device__ __forceinline__ void mma_tf32(float& d0, float& d1, float& d2, float& d3,
                                         uint32_t a0, uint32_t a1, uint32_t a2, uint32_t a3,
                                         uint32_t b0, uint32_t b1) {
    asm volatile(
        "mma.sync.aligned.m16n8k8.row.col.f32.tf32.tf32.f32 "
        "{%0,%1,%2,%3}, {%4,%5,%6,%7}, {%8,%9}, {%0,%1,%2,%3};"
        : "+f"(d0), "+f"(d1), "+f"(d2), "+f"(d3)
        : "r"(a0), "r"(a1), "r"(a2), "r"(a3), "r"(b0), "r"(b1));
}

// =============== tf32 mma.sync GEMM: C[M,N] = scale*(A[M,K] @ B[Nb,K]^T) + bias ===============
// grid = (ceil(Ncols/BN), M/BM), block = 128 (4 warps, 2x2 grid of 64x64 warp tiles)
__global__ void __launch_bounds__(128)
gemm_mma(const float* __restrict__ A, const float* __restrict__ B,
         const float* __restrict__ bias, float* __restrict__ C,
         float scale, int Ncols, int Nb, int K, int ldc, int trunc)
{
    extern __shared__ float sm[];

    const int tid  = threadIdx.x;
    const int wid  = tid >> 5;
    const int lane = tid & 31;
    const int gid  = lane >> 2;      // 0..7
    const int tig  = lane & 3;       // 0..3
    const int warpM = wid & 1;       // 2 warps along M (64 rows each)
    const int warpN = wid >> 1;      // 2 warps along N (64 cols each)
    const int mbase = blockIdx.y * BM;
    const int nbase = blockIdx.x * BN;

    // ---- gmem load mapping: 8 chunks of 16B per thread per tile ----
    const int lr = tid >> 3;            // 0..15 (row group)
    const int lc = tid & 7;             // 0..7  (16B chunk within 128B row)
    const float* Ag = A + (size_t)(mbase + lr) * K + lc * 4;
    // B rows may exceed Nb (fc epilogue): clamp pointer, zero-fill via cp.async size
    const uint32_t smem_base = smem_u32(sm);

    float acc[4][8][4];
    #pragma unroll
    for (int mf = 0; mf < 4; mf++)
        #pragma unroll
        for (int nf = 0; nf < 8; nf++)
            #pragma unroll
            for (int rr = 0; rr < 4; rr++) acc[mf][nf][rr] = 0.f;

    const int Kc = K / BK;

    // ---- stage prefetch helper (as a lambda-like macro) ----
    #define PREFETCH(T, SLOT) do {                                                 \
        const int _sf = (SLOT) * STAGE_FLOATS;                                     \
        const uint32_t _sa = smem_base + _sf * 4;                                  \
        const uint32_t _sb = smem_base + (_sf + A_TILE_FLOATS) * 4;                \
        const int _k0 = (T) * BK;                                                  \
        _Pragma("unroll")                                                          \
        for (int i = 0; i < 8; i++) {                                              \
            const int r = lr + i * 16;                                             \
            cp16(_sa + swz(r, lc * 4) * 4, Ag + (size_t)i * 16 * K + _k0);         \
        }                                                                          \
        _Pragma("unroll")                                                          \
        for (int i = 0; i < 8; i++) {                                              \
            const int r = lr + i * 16;                                             \
            const int gr = nbase + r;                                              \
            const int v = gr < Nb;                                                 \
            const float* bp = B + (size_t)(v ? gr : 0) * K + _k0 + lc * 4;         \
            cp16z(_sb + swz(r, lc * 4) * 4, bp, v);                                \
        }                                                                          \
    } while (0)

    PREFETCH(0, 0);
    asm volatile("cp.async.commit_group;");
    if (Kc > 1) PREFETCH(1, 1);
    asm volatile("cp.async.commit_group;");

    for (int t = 0; t < Kc; t++) {
        asm volatile("cp.async.wait_group 1;");
        __syncthreads();
        if (t + 2 < Kc) PREFETCH(t + 2, (t + 2) % STAGES);
        asm volatile("cp.async.commit_group;");

        const float* sA = sm + (t % STAGES) * STAGE_FLOATS;
        const float* sB = sA + A_TILE_FLOATS;
        const uint32_t* uA = (const uint32_t*)sA;
        const uint32_t* uB = (const uint32_t*)sB;

        #pragma unroll
        for (int ks = 0; ks < 4; ks++) {
            const int K0 = ks * 8;
            uint32_t af[4][4], bf[8][2];
            #pragma unroll
            for (int mf = 0; mf < 4; mf++) {
                const int r0 = warpM * 64 + mf * 16 + gid;
                af[mf][0] = uA[swz(r0,     K0 + tig)];
                af[mf][1] = uA[swz(r0 + 8, K0 + tig)];
                af[mf][2] = uA[swz(r0,     K0 + tig + 4)];
                af[mf][3] = uA[swz(r0 + 8, K0 + tig + 4)];
            }
            #pragma unroll
            for (int nf = 0; nf < 8; nf++) {
                const int n0 = warpN * 64 + nf * 8 + gid;
                bf[nf][0] = uB[swz(n0, K0 + tig)];
                bf[nf][1] = uB[swz(n0, K0 + tig + 4)];
            }
            #pragma unroll
            for (int mf = 0; mf < 4; mf++)
                #pragma unroll
                for (int nf = 0; nf < 8; nf++)
                    mma_tf32(acc[mf][nf][0], acc[mf][nf][1], acc[mf][nf][2], acc[mf][nf][3],
                             af[mf][0], af[mf][1], af[mf][2], af[mf][3],
                             bf[nf][0], bf[nf][1]);
        }
        __syncthreads();
    }
    #undef PREFETCH

    // ---- epilogue ----
    #pragma unroll
    for (int mf = 0; mf < 4; mf++) {
        const int r0 = mbase + warpM * 64 + mf * 16 + gid;
        #pragma unroll
        for (int nf = 0; nf < 8; nf++) {
            const int col = nbase + warpN * 64 + nf * 8 + tig * 2;
            float v0 = acc[mf][nf][0] * scale;
            float v1 = acc[mf][nf][1] * scale;
            float v2 = acc[mf][nf][2] * scale;
            float v3 = acc[mf][nf][3] * scale;
            if (bias) {
                const float bz0 = (col < Ncols) ? __ldg(bias + col) : 0.f;
                const float bz1 = (col + 1 < Ncols) ? __ldg(bias + col + 1) : 0.f;
                v0 += bz0; v1 += bz1; v2 += bz0; v3 += bz1;
            }
            if (trunc) { v0 = tf32r(v0); v1 = tf32r(v1); v2 = tf32r(v2); v3 = tf32r(v3); }
            if (col + 1 < Ncols) {
                *(float2*)(C + (size_t)r0 * ldc + col)       = make_float2(v0, v1);
                *(float2*)(C + (size_t)(r0 + 8) * ldc + col) = make_float2(v2, v3);
            } else if (col < Ncols) {
                C[(size_t)r0 * ldc + col]       = v0;
                C[(size_t)(r0 + 8) * ldc + col] = v2;
            }
        }
    }
}

// =============== x -> tf32-rounded copy ===============
__global__ void __launch_bounds__(256)
trunc_copy(const float* __restrict__ in, float* __restrict__ out, int n4)
{
    int i = blockIdx.x * 256 + threadIdx.x;
    if (i < n4) {
        float4 v = ((const float4*)in)[i];
        v.x = tf32r(v.x); v.y = tf32r(v.y); v.z = tf32r(v.z); v.w = tf32r(v.w);
        ((float4*)out)[i] = v;
    }
}

// =============== transpose (+ optional tf32 rounding): out[C,R] = in[R,C]^T ===============
__global__ void __launch_bounds__(256)
transpose_f(const float* __restrict__ in, float* __restrict__ out, int R, int C, int trunc)
{
    __shared__ float t[32][33];
    const int bx = blockIdx.x * 32, by = blockIdx.y * 32;
    const int txx = threadIdx.x, tyy = threadIdx.y;
    #pragma unroll
    for (int i = tyy; i < 32; i += 8) {
        int y = by + i, x = bx + txx;
        if (y < R && x < C) t[i][txx] = in[(size_t)y * C + x];
    }
    __syncthreads();
    #pragma unroll
    for (int i = tyy; i < 32; i += 8) {
        int oy = bx + i, ox = by + txx;
        if (oy < C && ox < R) {
            float v = t[txx][i];
            if (trunc) v = tf32r(v);
            out[(size_t)oy * R + ox] = v;
        }
    }
}

// =============== single-pass row softmax over 8192 cols (tf32-rounded output) ===============
__global__ void __launch_bounds__(256)
softmax_rows(float* __restrict__ S)
{
    const int row = blockIdx.x;
    float* p = S + (size_t)row * N_ROWS;
    const int tid = threadIdx.x;

    float v[32];
    float mx = -CUDART_INF_F;
    #pragma unroll
    for (int i = 0; i < 32; i++) { v[i] = p[tid + i * 256]; mx = fmaxf(mx, v[i]); }
    __shared__ float red[8];
    #pragma unroll
    for (int o = 16; o > 0; o >>= 1) mx = fmaxf(mx, __shfl_xor_sync(0xffffffffu, mx, o));
    if ((tid & 31) == 0) red[tid >> 5] = mx;
    __syncthreads();
    if (tid < 8) {
        float m = red[tid];
        #pragma unroll
        for (int o = 4; o > 0; o >>= 1) m = fmaxf(m, __shfl_xor_sync(0xffu, m, o));
        if (tid == 0) red[0] = m;
    }
    __syncthreads();
    mx = red[0];
    __syncthreads();

    float sum = 0.f;
    #pragma unroll
    for (int i = 0; i < 32; i++) { v[i] = __expf(v[i] - mx); sum += v[i]; }
    #pragma unroll
    for (int o = 16; o > 0; o >>= 1) sum += __shfl_xor_sync(0xffffffffu, sum, o);
    if ((tid & 31) == 0) red[tid >> 5] = sum;
    __syncthreads();
    if (tid < 8) {
        float s = red[tid];
        #pragma unroll
        for (int o = 4; o > 0; o >>= 1) s += __shfl_xor_sync(0xffu, s, o);
        if (tid == 0) red[0] = s;
    }
    __syncthreads();
    const float inv = 1.f / red[0];
    #pragma unroll
    for (int i = 0; i < 32; i++) p[tid + i * 256] = tf32r(v[i] * inv);
}

// =============== beta gate + mix (tf32-rounded m), one block per row ===============
__global__ void __launch_bounds__(256)
beta_mix(const float* __restrict__ a, const float* __restrict__ xr,
         const float* __restrict__ Wb, const float* __restrict__ bb,
         float* __restrict__ Mout)
{
    const int row = blockIdx.x;
    const int tid = threadIdx.x;
    const float* ap = a  + (size_t)row * DIM;
    const float* xp = xr + (size_t)row * DIM;

    float partial = 0.f;
    #pragma unroll
    for (int i = tid; i < DIM; i += 256) {
        float av = ap[i], xv = xp[i];
        partial += av * Wb[i] + xv * Wb[DIM + i] + (av - xv) * Wb[2 * DIM + i];
    }
    __shared__ float red[8];
    #pragma unroll
    for (int o = 16; o > 0; o >>= 1) partial += __shfl_xor_sync(0xffffffffu, partial, o);
    if ((tid & 31) == 0) red[tid >> 5] = partial;
    __syncthreads();
    __shared__ float s_beta;
    if (tid == 0) {
        float t = 0.f;
        #pragma unroll
        for (int w = 0; w < 8; w++) t += red[w];
        t += bb[0];
        s_beta = 1.f / (1.f + expf(-t));
    }
    __syncthreads();
    const float beta = s_beta;
    float* mp = Mout + (size_t)row * DIM;
    #pragma unroll
    for (int i = tid; i < DIM; i += 256)
        mp[i] = tf32r(beta * xp[i] + (1.f - beta) * ap[i]);
}

// =============== launch ===============
extern "C" void kernel_launch(void* const* d_in, const int* in_sizes, int n_in,
                              void* d_out, int out_size)
{
    const float* x      = (const float*)d_in[0];
    const float* W_skip = (const float*)d_in[1];
    const float* b_skip = (const float*)d_in[2];
    const float* W_q    = (const float*)d_in[3];
    const float* b_q    = (const float*)d_in[4];
    const float* W_k    = (const float*)d_in[5];
    const float* b_k    = (const float*)d_in[6];
    const float* W_v    = (const float*)d_in[7];
    const float* b_v    = (const float*)d_in[8];
    const float* W_beta = (const float*)d_in[9];
    const float* b_beta = (const float*)d_in[10];
    const float* W_fc   = (const float*)d_in[11];
    const float* b_fc   = (const float*)d_in[12];
    float* out = (float*)d_out;

    float *xt, *q, *k, *v, *xr, *S, *a, *m, *vT, *WqT, *WkT, *WvT, *WsT, *WfcT;
    cudaGetSymbolAddress((void**)&xt,  g_xt);
    cudaGetSymbolAddress((void**)&q,   g_q);
    cudaGetSymbolAddress((void**)&k,   g_k);
    cudaGetSymbolAddress((void**)&v,   g_v);
    cudaGetSymbolAddress((void**)&xr,  g_xr);
    cudaGetSymbolAddress((void**)&S,   g_S);
    cudaGetSymbolAddress((void**)&a,   g_a);
    cudaGetSymbolAddress((void**)&m,   g_m);
    cudaGetSymbolAddress((void**)&vT,  g_vT);
    cudaGetSymbolAddress((void**)&WqT, g_WqT);
    cudaGetSymbolAddress((void**)&WkT, g_WkT);
    cudaGetSymbolAddress((void**)&WvT, g_WvT);
    cudaGetSymbolAddress((void**)&WsT, g_WsT);
    cudaGetSymbolAddress((void**)&WfcT,g_WfcT);

    cudaFuncSetAttribute(gemm_mma, cudaFuncAttributeMaxDynamicSharedMemorySize, DYN_SMEM);

    dim3 tb(32, 8);
    // operand conditioning: transpose weights (K-major B operands) + tf32 rounding
    transpose_f<<<dim3(32, 32), tb>>>(W_q,    WqT, DIM, DIM, 1);
    transpose_f<<<dim3(32, 32), tb>>>(W_k,    WkT, DIM, DIM, 1);
    transpose_f<<<dim3(32, 32), tb>>>(W_v,    WvT, DIM, DIM, 1);
    transpose_f<<<dim3(32, 32), tb>>>(W_skip, WsT, DIM, DIM, 1);
    transpose_f<<<dim3((NCLS + 31) / 32, 32), tb>>>(W_fc, WfcT, DIM, NCLS, 1);
    trunc_copy<<<(N_ROWS * DIM / 4 + 255) / 256, 256>>>(x, xt, N_ROWS * DIM / 4);

    const dim3 blk(128);
    const dim3 gProj(DIM / BN, N_ROWS / BM);            // (8, 64)
    // q,k outputs rounded to tf32 (they feed the scores GEMM); v rounded in its transpose; xr stays fp32
    gemm_mma<<<gProj, blk, DYN_SMEM>>>(xt, WqT, b_q,    q,  1.f, DIM, DIM, DIM, DIM, 1);
    gemm_mma<<<gProj, blk, DYN_SMEM>>>(xt, WkT, b_k,    k,  1.f, DIM, DIM, DIM, DIM, 1);
    gemm_mma<<<gProj, blk, DYN_SMEM>>>(xt, WvT, b_v,    v,  1.f, DIM, DIM, DIM, DIM, 0);
    gemm_mma<<<gProj, blk, DYN_SMEM>>>(xt, WsT, b_skip, xr, 1.f, DIM, DIM, DIM, DIM, 0);

    transpose_f<<<dim3(DIM / 32, N_ROWS / 32), tb>>>(v, vT, N_ROWS, DIM, 1);

    const dim3 gScore(N_ROWS / BN, N_ROWS / BM);        // (64, 64)
    gemm_mma<<<gScore, blk, DYN_SMEM>>>(q, k, nullptr, S, 1.f / 32.f, N_ROWS, N_ROWS, DIM, N_ROWS, 0);

    softmax_rows<<<N_ROWS, 256>>>(S);

    gemm_mma<<<gProj, blk, DYN_SMEM>>>(S, vT, nullptr, a, 1.f, DIM, DIM, N_ROWS, DIM, 0);

    beta_mix<<<N_ROWS, 256>>>(a, xr, W_beta, b_beta, m);

    const dim3 gFc((NCLS + BN - 1) / BN, N_ROWS / BM);  // (8, 64)
    gemm_mma<<<gFc, blk, DYN_SMEM>>>(m, WfcT, b_fc, out, 1.f, NCLS, NCLS, DIM, NCLS, 0);
}

// round 5
// speedup vs baseline: 7.6042x; 1.7929x over previous
#include <cuda_runtime.h>
#include <cuda_fp16.h>
#include <math_constants.h>
#include <cstdint>

#define N_ROWS 8192
#define DIM    1024
#define NCLS   1000

// ---- fp16 mma.sync GEMM tile config ----
#define BM 128
#define BN 128
#define BKH 64                                  // halves per K-chunk (128B row)
#define STAGES 3
#define A_TILE_WORDS (BM * BKH / 2)             // 4096 32-bit words (16KB)
#define STAGE_WORDS  (2 * A_TILE_WORDS)         // 8192 words (32KB)
#define DYN_SMEM     (STAGES * STAGE_WORDS * 4) // 96KB

// ---------------- scratch (device globals: allocation-free) ----------------
__device__ __half g_xh [N_ROWS * DIM];
__device__ __half g_qh [N_ROWS * DIM];
__device__ __half g_kh [N_ROWS * DIM];
__device__ float  g_v  [N_ROWS * DIM];
__device__ float  g_xr [N_ROWS * DIM];
__device__ float  g_a  [N_ROWS * DIM];
__device__ __half g_mh [N_ROWS * DIM];
__device__ __half g_vTh[DIM * N_ROWS];
__device__ __half g_Sh [(size_t)N_ROWS * N_ROWS];   // 128 MB fp16 scores
__device__ __half g_WqT [DIM * DIM];
__device__ __half g_WkT [DIM * DIM];
__device__ __half g_WvT [DIM * DIM];
__device__ __half g_WsT [DIM * DIM];
__device__ __half g_WfcT[NCLS * DIM];

// ================= helpers =================
__device__ __forceinline__ uint32_t smem_u32(const void* p) {
    uint32_t a;
    asm("{ .reg .u64 t; cvta.to.shared.u64 t, %1; cvt.u32.u64 %0, t; }" : "=r"(a) : "l"(p));
    return a;
}
// word-granular XOR swizzle: (row r, 32-bit word w in 0..31) -> word offset
__device__ __forceinline__ int swzw(int r, int w) {
    return r * 32 + (w ^ ((r & 7) << 2));
}
__device__ __forceinline__ void cp16(uint32_t saddr, const void* g) {
    asm volatile("cp.async.cg.shared.global [%0], [%1], 16;" :: "r"(saddr), "l"(g));
}
__device__ __forceinline__ void cp16z(uint32_t saddr, const void* g, int valid) {
    int sz = valid ? 16 : 0;
    asm volatile("cp.async.cg.shared.global [%0], [%1], 16, %2;" :: "r"(saddr), "l"(g), "r"(sz));
}
__device__ __forceinline__ void mma_f16(float& d0, float& d1, float& d2, float& d3,
                                        uint32_t a0, uint32_t a1, uint32_t a2, uint32_t a3,
                                        uint32_t b0, uint32_t b1) {
    asm volatile(
        "mma.sync.aligned.m16n8k16.row.col.f32.f16.f16.f32 "
        "{%0,%1,%2,%3}, {%4,%5,%6,%7}, {%8,%9}, {%0,%1,%2,%3};"
        : "+f"(d0), "+f"(d1), "+f"(d2), "+f"(d3)
        : "r"(a0), "r"(a1), "r"(a2), "r"(a3), "r"(b0), "r"(b1));
}

// =============== fp16 mma GEMM: C = scale*(A[M,K]h @ B[Nb,K]h^T) + bias ===============
// grid = (ceil(Ncols/BN), M/BM), block = 128 (4 warps, 2x2 of 64x64 warp tiles)
__global__ void __launch_bounds__(128)
gemm_h(const __half* __restrict__ A, const __half* __restrict__ B,
       const float* __restrict__ bias, void* __restrict__ Cv,
       int out_half, float scale, int Ncols, int Nb, int K, int ldc)
{
    extern __shared__ uint32_t sm32[];

    const int tid  = threadIdx.x;
    const int wid  = tid >> 5;
    const int lane = tid & 31;
    const int gid  = lane >> 2;
    const int tig  = lane & 3;
    const int warpM = wid & 1;
    const int warpN = wid >> 1;
    const int mbase = blockIdx.y * BM;
    const int nbase = blockIdx.x * BN;

    const int lr = tid >> 3;            // 0..15
    const int lc = tid & 7;             // 0..7 (16B chunk)
    const __half* Ag = A + (size_t)(mbase + lr) * K + lc * 8;
    const uint32_t smem_base = smem_u32(sm32);

    float acc[4][8][4];
    #pragma unroll
    for (int mf = 0; mf < 4; mf++)
        #pragma unroll
        for (int nf = 0; nf < 8; nf++)
            #pragma unroll
            for (int rr = 0; rr < 4; rr++) acc[mf][nf][rr] = 0.f;

    const int Kc = K / BKH;

    #define PREFETCH(T, SLOT) do {                                                 \
        const uint32_t _sa = smem_base + (SLOT) * STAGE_WORDS * 4;                 \
        const uint32_t _sb = _sa + A_TILE_WORDS * 4;                               \
        const int _k0 = (T) * BKH;                                                 \
        _Pragma("unroll")                                                          \
        for (int i = 0; i < 8; i++) {                                              \
            const int r = lr + i * 16;                                             \
            cp16(_sa + swzw(r, lc * 4) * 4, Ag + (size_t)i * 16 * K + _k0);        \
        }                                                                          \
        _Pragma("unroll")                                                          \
        for (int i = 0; i < 8; i++) {                                              \
            const int r = lr + i * 16;                                             \
            const int gr = nbase + r;                                              \
            const int vld = gr < Nb;                                               \
            const __half* bp = B + (size_t)(vld ? gr : 0) * K + _k0 + lc * 8;      \
            cp16z(_sb + swzw(r, lc * 4) * 4, bp, vld);                             \
        }                                                                          \
    } while (0)

    PREFETCH(0, 0);
    asm volatile("cp.async.commit_group;");
    if (Kc > 1) PREFETCH(1, 1);
    asm volatile("cp.async.commit_group;");

    for (int t = 0; t < Kc; t++) {
        asm volatile("cp.async.wait_group 1;");
        __syncthreads();
        if (t + 2 < Kc) PREFETCH(t + 2, (t + 2) % STAGES);
        asm volatile("cp.async.commit_group;");

        const uint32_t* uA = sm32 + (t % STAGES) * STAGE_WORDS;
        const uint32_t* uB = uA + A_TILE_WORDS;

        #pragma unroll
        for (int ks = 0; ks < 4; ks++) {          // 4 k16 steps per BKH=64
            const int W0 = ks * 8;
            uint32_t af[4][4], bf[8][2];
            #pragma unroll
            for (int mf = 0; mf < 4; mf++) {
                const int r0 = warpM * 64 + mf * 16 + gid;
                af[mf][0] = uA[swzw(r0,     W0 + tig)];
                af[mf][1] = uA[swzw(r0 + 8, W0 + tig)];
                af[mf][2] = uA[swzw(r0,     W0 + tig + 4)];
                af[mf][3] = uA[swzw(r0 + 8, W0 + tig + 4)];
            }
            #pragma unroll
            for (int nf = 0; nf < 8; nf++) {
                const int n0 = warpN * 64 + nf * 8 + gid;
                bf[nf][0] = uB[swzw(n0, W0 + tig)];
                bf[nf][1] = uB[swzw(n0, W0 + tig + 4)];
            }
            #pragma unroll
            for (int mf = 0; mf < 4; mf++)
                #pragma unroll
                for (int nf = 0; nf < 8; nf++)
                    mma_f16(acc[mf][nf][0], acc[mf][nf][1], acc[mf][nf][2], acc[mf][nf][3],
                            af[mf][0], af[mf][1], af[mf][2], af[mf][3],
                            bf[nf][0], bf[nf][1]);
        }
        __syncthreads();
    }
    #undef PREFETCH

    // ---- epilogue ----
    float* Cf = (float*)Cv;
    __half* Ch = (__half*)Cv;
    #pragma unroll
    for (int mf = 0; mf < 4; mf++) {
        const int r0 = mbase + warpM * 64 + mf * 16 + gid;
        #pragma unroll
        for (int nf = 0; nf < 8; nf++) {
            const int col = nbase + warpN * 64 + nf * 8 + tig * 2;
            float v0 = acc[mf][nf][0] * scale;
            float v1 = acc[mf][nf][1] * scale;
            float v2 = acc[mf][nf][2] * scale;
            float v3 = acc[mf][nf][3] * scale;
            if (bias) {
                const float bz0 = (col < Ncols) ? __ldg(bias + col) : 0.f;
                const float bz1 = (col + 1 < Ncols) ? __ldg(bias + col + 1) : 0.f;
                v0 += bz0; v1 += bz1; v2 += bz0; v3 += bz1;
            }
            if (out_half) {
                if (col + 1 < Ncols) {
                    *(__half2*)(Ch + (size_t)r0 * ldc + col)       = __floats2half2_rn(v0, v1);
                    *(__half2*)(Ch + (size_t)(r0 + 8) * ldc + col) = __floats2half2_rn(v2, v3);
                } else if (col < Ncols) {
                    Ch[(size_t)r0 * ldc + col]       = __float2half_rn(v0);
                    Ch[(size_t)(r0 + 8) * ldc + col] = __float2half_rn(v2);
                }
            } else {
                if (col + 1 < Ncols) {
                    *(float2*)(Cf + (size_t)r0 * ldc + col)       = make_float2(v0, v1);
                    *(float2*)(Cf + (size_t)(r0 + 8) * ldc + col) = make_float2(v2, v3);
                } else if (col < Ncols) {
                    Cf[(size_t)r0 * ldc + col]       = v0;
                    Cf[(size_t)(r0 + 8) * ldc + col] = v2;
                }
            }
        }
    }
}

// =============== x -> fp16 copy ===============
__global__ void __launch_bounds__(256)
half_copy(const float* __restrict__ in, __half* __restrict__ out, int n8)
{
    int i = blockIdx.x * 256 + threadIdx.x;
    if (i < n8) {
        float4 f0 = ((const float4*)in)[2 * i];
        float4 f1 = ((const float4*)in)[2 * i + 1];
        __half2 h0 = __floats2half2_rn(f0.x, f0.y);
        __half2 h1 = __floats2half2_rn(f0.z, f0.w);
        __half2 h2 = __floats2half2_rn(f1.x, f1.y);
        __half2 h3 = __floats2half2_rn(f1.z, f1.w);
        uint4 o;
        o.x = *(uint32_t*)&h0; o.y = *(uint32_t*)&h1;
        o.z = *(uint32_t*)&h2; o.w = *(uint32_t*)&h3;
        ((uint4*)out)[i] = o;
    }
}

// =============== transpose fp32 -> fp16: out[C,R] = half(in[R,C]^T) ===============
__global__ void __launch_bounds__(256)
transpose_h(const float* __restrict__ in, __half* __restrict__ out, int R, int C)
{
    __shared__ float t[32][33];
    const int bx = blockIdx.x * 32, by = blockIdx.y * 32;
    const int txx = threadIdx.x, tyy = threadIdx.y;
    #pragma unroll
    for (int i = tyy; i < 32; i += 8) {
        int y = by + i, x = bx + txx;
        if (y < R && x < C) t[i][txx] = in[(size_t)y * C + x];
    }
    __syncthreads();
    #pragma unroll
    for (int i = tyy; i < 32; i += 8) {
        int oy = bx + i, ox = by + txx;
        if (oy < C && ox < R) out[(size_t)oy * R + ox] = __float2half_rn(t[txx][i]);
    }
}

// =============== single-pass row softmax over 8192 fp16 cols ===============
__global__ void __launch_bounds__(256)
softmax_h(__half* __restrict__ S)
{
    const int row = blockIdx.x;
    __half2* p = (__half2*)(S + (size_t)row * N_ROWS);
    const int tid = threadIdx.x;

    float2 v[16];
    float mx = -CUDART_INF_F;
    #pragma unroll
    for (int i = 0; i < 16; i++) {
        v[i] = __half22float2(p[tid + i * 256]);
        mx = fmaxf(mx, fmaxf(v[i].x, v[i].y));
    }
    __shared__ float red[8];
    #pragma unroll
    for (int o = 16; o > 0; o >>= 1) mx = fmaxf(mx, __shfl_xor_sync(0xffffffffu, mx, o));
    if ((tid & 31) == 0) red[tid >> 5] = mx;
    __syncthreads();
    if (tid < 8) {
        float m = red[tid];
        #pragma unroll
        for (int o = 4; o > 0; o >>= 1) m = fmaxf(m, __shfl_xor_sync(0xffu, m, o));
        if (tid == 0) red[0] = m;
    }
    __syncthreads();
    mx = red[0];
    __syncthreads();

    float sum = 0.f;
    #pragma unroll
    for (int i = 0; i < 16; i++) {
        v[i].x = __expf(v[i].x - mx);
        v[i].y = __expf(v[i].y - mx);
        sum += v[i].x + v[i].y;
    }
    #pragma unroll
    for (int o = 16; o > 0; o >>= 1) sum += __shfl_xor_sync(0xffffffffu, sum, o);
    if ((tid & 31) == 0) red[tid >> 5] = sum;
    __syncthreads();
    if (tid < 8) {
        float s = red[tid];
        #pragma unroll
        for (int o = 4; o > 0; o >>= 1) s += __shfl_xor_sync(0xffu, s, o);
        if (tid == 0) red[0] = s;
    }
    __syncthreads();
    const float inv = 1.f / red[0];
    #pragma unroll
    for (int i = 0; i < 16; i++)
        p[tid + i * 256] = __floats2half2_rn(v[i].x * inv, v[i].y * inv);
}

// =============== beta gate + mix -> fp16 m, one block per row ===============
__global__ void __launch_bounds__(256)
beta_mix(const float* __restrict__ a, const float* __restrict__ xr,
         const float* __restrict__ Wb, const float* __restrict__ bb,
         __half* __restrict__ Mout)
{
    const int row = blockIdx.x;
    const int tid = threadIdx.x;
    const float* ap = a  + (size_t)row * DIM;
    const float* xp = xr + (size_t)row * DIM;

    float partial = 0.f;
    #pragma unroll
    for (int i = tid; i < DIM; i += 256) {
        float av = ap[i], xv = xp[i];
        partial += av * Wb[i] + xv * Wb[DIM + i] + (av - xv) * Wb[2 * DIM + i];
    }
    __shared__ float red[8];
    #pragma unroll
    for (int o = 16; o > 0; o >>= 1) partial += __shfl_xor_sync(0xffffffffu, partial, o);
    if ((tid & 31) == 0) red[tid >> 5] = partial;
    __syncthreads();
    __shared__ float s_beta;
    if (tid == 0) {
        float t = 0.f;
        #pragma unroll
        for (int w = 0; w < 8; w++) t += red[w];
        t += bb[0];
        s_beta = 1.f / (1.f + expf(-t));
    }
    __syncthreads();
    const float beta = s_beta;
    __half* mp = Mout + (size_t)row * DIM;
    #pragma unroll
    for (int i = tid; i < DIM; i += 256)
        mp[i] = __float2half_rn(beta * xp[i] + (1.f - beta) * ap[i]);
}

// =============== launch ===============
extern "C" void kernel_launch(void* const* d_in, const int* in_sizes, int n_in,
                              void* d_out, int out_size)
{
    const float* x      = (const float*)d_in[0];
    const float* W_skip = (const float*)d_in[1];
    const float* b_skip = (const float*)d_in[2];
    const float* W_q    = (const float*)d_in[3];
    const float* b_q    = (const float*)d_in[4];
    const float* W_k    = (const float*)d_in[5];
    const float* b_k    = (const float*)d_in[6];
    const float* W_v    = (const float*)d_in[7];
    const float* b_v    = (const float*)d_in[8];
    const float* W_beta = (const float*)d_in[9];
    const float* b_beta = (const float*)d_in[10];
    const float* W_fc   = (const float*)d_in[11];
    const float* b_fc   = (const float*)d_in[12];
    float* out = (float*)d_out;

    __half *xh, *qh, *kh, *mh, *vTh, *Sh, *WqT, *WkT, *WvT, *WsT, *WfcT;
    float *v, *xr, *a;
    cudaGetSymbolAddress((void**)&xh,  g_xh);
    cudaGetSymbolAddress((void**)&qh,  g_qh);
    cudaGetSymbolAddress((void**)&kh,  g_kh);
    cudaGetSymbolAddress((void**)&v,   g_v);
    cudaGetSymbolAddress((void**)&xr,  g_xr);
    cudaGetSymbolAddress((void**)&a,   g_a);
    cudaGetSymbolAddress((void**)&mh,  g_mh);
    cudaGetSymbolAddress((void**)&vTh, g_vTh);
    cudaGetSymbolAddress((void**)&Sh,  g_Sh);
    cudaGetSymbolAddress((void**)&WqT, g_WqT);
    cudaGetSymbolAddress((void**)&WkT, g_WkT);
    cudaGetSymbolAddress((void**)&WvT, g_WvT);
    cudaGetSymbolAddress((void**)&WsT, g_WsT);
    cudaGetSymbolAddress((void**)&WfcT,g_WfcT);

    cudaFuncSetAttribute(gemm_h, cudaFuncAttributeMaxDynamicSharedMemorySize, DYN_SMEM);

    const dim3 tb(32, 8);
    const dim3 blk(128);
    const dim3 gProj(DIM / BN, N_ROWS / BM);            // (8, 64)
    const dim3 gScore(N_ROWS / BN, N_ROWS / BM);        // (64, 64)
    const dim3 gFc((NCLS + BN - 1) / BN, N_ROWS / BM);  // (8, 64)

    // launch order arranged so ncu (-s 5 -c 1) captures the scores GEMM
    half_copy<<<(N_ROWS * DIM / 8 + 255) / 256, 256>>>(x, xh, N_ROWS * DIM / 8);     // 0
    transpose_h<<<dim3(32, 32), tb>>>(W_q, WqT, DIM, DIM);                            // 1
    transpose_h<<<dim3(32, 32), tb>>>(W_k, WkT, DIM, DIM);                            // 2
    gemm_h<<<gProj, blk, DYN_SMEM>>>(xh, WqT, b_q, qh, 1, 1.f, DIM, DIM, DIM, DIM);   // 3
    gemm_h<<<gProj, blk, DYN_SMEM>>>(xh, WkT, b_k, kh, 1, 1.f, DIM, DIM, DIM, DIM);   // 4
    gemm_h<<<gScore, blk, DYN_SMEM>>>(qh, kh, nullptr, Sh, 1, 1.f / 32.f,
                                      N_ROWS, N_ROWS, DIM, N_ROWS);                   // 5 <- ncu
    transpose_h<<<dim3(32, 32), tb>>>(W_v,    WvT, DIM, DIM);
    transpose_h<<<dim3(32, 32), tb>>>(W_skip, WsT, DIM, DIM);
    transpose_h<<<dim3((NCLS + 31) / 32, 32), tb>>>(W_fc, WfcT, DIM, NCLS);
    gemm_h<<<gProj, blk, DYN_SMEM>>>(xh, WvT, b_v,    v,  0, 1.f, DIM, DIM, DIM, DIM);
    gemm_h<<<gProj, blk, DYN_SMEM>>>(xh, WsT, b_skip, xr, 0, 1.f, DIM, DIM, DIM, DIM);
    transpose_h<<<dim3(DIM / 32, N_ROWS / 32), tb>>>(v, vTh, N_ROWS, DIM);

    softmax_h<<<N_ROWS, 256>>>(Sh);

    gemm_h<<<gProj, blk, DYN_SMEM>>>(Sh, vTh, nullptr, a, 0, 1.f, DIM, DIM, N_ROWS, DIM);

    beta_mix<<<N_ROWS, 256>>>(a, xr, W_beta, b_beta, mh);

    gemm_h<<<gFc, blk, DYN_SMEM>>>(mh, WfcT, b_fc, out, 0, 1.f, NCLS, NCLS, DIM, NCLS);
}